// round 6
// baseline (speedup 1.0000x reference)
#include <cuda_runtime.h>
#include <stdint.h>

typedef unsigned long long u64;
typedef unsigned int u32;

// ---------------- constant-memory weights ----------------
__constant__ __align__(16) float cW1[64 * 64];
__constant__ __align__(16) float cW2[64 * 16];
__constant__ __align__(16) float cW3[16 * 8];
__constant__ __align__(16) float cW4[8 * 3];
__constant__ __align__(16) float cB1[64];
__constant__ __align__(16) float cB2[16];
__constant__ __align__(16) float cB3[8];
__constant__ __align__(16) float cB4[3];
__constant__ __align__(16) float cEnc[27];

// ---------------- helpers ----------------
static __device__ __forceinline__ u64 pack2(float lo, float hi) {
    u64 r; asm("mov.b64 %0, {%1, %2};" : "=l"(r) : "f"(lo), "f"(hi)); return r;
}
static __device__ __forceinline__ float2 unpack2(u64 v) {
    float2 f; asm("mov.b64 {%0, %1}, %2;" : "=f"(f.x), "=f"(f.y) : "l"(v)); return f;
}
static __device__ __forceinline__ void fma2(u64 &d, u64 a, u64 b) {
    asm("fma.rn.f32x2 %0, %1, %2, %0;" : "+l"(d) : "l"(a), "l"(b));
}
static __device__ __forceinline__ float leaky(float x) { return fmaxf(x, 0.01f * x); }
static __device__ __forceinline__ float sigmoidf(float x) { return 1.0f / (1.0f + __expf(-x)); }
static __device__ __forceinline__ float tanh_fast(float x) {
    return fmaf(2.0f, sigmoidf(2.0f * x), -1.0f);
}

static __device__ __forceinline__ void encode(float i0, float i1, float &x, float &y) {
    float h[4];
#pragma unroll
    for (int j = 0; j < 4; j++)
        h[j] = tanh_fast(fmaf(i0, cEnc[j], fmaf(i1, cEnc[4 + j], cEnc[8 + j])));
    float z0 = cEnc[24], z1 = cEnc[25];
#pragma unroll
    for (int j = 0; j < 4; j++) {
        z0 = fmaf(h[j], cEnc[12 + j * 3 + 0], z0);
        z1 = fmaf(h[j], cEnc[12 + j * 3 + 1], z1);
    }
    x = sigmoidf(z0) * 255.0f;
    y = sigmoidf(z1) * 255.0f;
}

// FC3 (16->8) + FC4 (8->3) + sigmoid*255 (constant: tiny traffic)
static __device__ __forceinline__ float3 head(const float *a2) {
    u64 h3[4];
#pragma unroll
    for (int q = 0; q < 4; q++) h3[q] = pack2(cB3[2 * q], cB3[2 * q + 1]);
#pragma unroll
    for (int j = 0; j < 16; j++) {
        float a = a2[j];
        u64 av = pack2(a, a);
        const ulonglong2 *w = (const ulonglong2 *)(cW3 + j * 8);
#pragma unroll
        for (int q = 0; q < 2; q++) {
            ulonglong2 wq = w[q];
            fma2(h3[2 * q], av, wq.x);
            fma2(h3[2 * q + 1], av, wq.y);
        }
    }
    float o0 = cB4[0], o1 = cB4[1], o2 = cB4[2];
#pragma unroll
    for (int q = 0; q < 4; q++) {
        float2 v = unpack2(h3[q]);
        float a0 = leaky(v.x), a1 = leaky(v.y);
        int i0 = 2 * q, i1 = 2 * q + 1;
        o0 = fmaf(a0, cW4[i0 * 3 + 0], o0);
        o1 = fmaf(a0, cW4[i0 * 3 + 1], o1);
        o2 = fmaf(a0, cW4[i0 * 3 + 2], o2);
        o0 = fmaf(a1, cW4[i1 * 3 + 0], o0);
        o1 = fmaf(a1, cW4[i1 * 3 + 1], o1);
        o2 = fmaf(a1, cW4[i1 * 3 + 2], o2);
    }
    float3 r;
    r.x = sigmoidf(leaky(o0)) * 255.0f;
    r.y = sigmoidf(leaky(o1)) * 255.0f;
    r.z = sigmoidf(leaky(o2)) * 255.0f;
    return r;
}

#define SLOTS 11  // 8 feature slots + 3 pad -> stride 44 floats, conflict-free readback

// ---------------- kernel ----------------
__global__ void __launch_bounds__(128, 5) gridnet_split(
    const float *__restrict__ pos, const float *__restrict__ dir,
    const float *__restrict__ pos_grid, const float *__restrict__ dir_grid,
    float *__restrict__ out, int n, int ntiles)
{
    __shared__ __align__(16) float4 s_stage[4][32][SLOTS];  // 22528B
    __shared__ __align__(8) u64 s_meta[4][32][8];           // 8192B
    __shared__ __align__(16) float sW1p[64][36];            // 9216B: FC1 outs 0..35
    __shared__ __align__(16) float sW2p[64][12];            // 3072B: FC2 outs 0..11
    __shared__ __align__(8) u64 sB1p[32];
    __shared__ __align__(8) u64 sB2p[8];

    const int tid = threadIdx.x;
    const int warp = tid >> 5, lane = tid & 31;
    const int grp = lane >> 3, f = lane & 7;

    // ---- stage split weights const -> shared (once per CTA)
    if (tid < 64) {
#pragma unroll
        for (int k = 0; k < 36; k++) sW1p[tid][k] = cW1[tid * 64 + k];
    } else {
        int r = tid - 64;
#pragma unroll
        for (int k = 0; k < 12; k++) sW2p[r][k] = cW2[r * 16 + k];
    }
    if (tid < 32) sB1p[tid] = pack2(cB1[2 * tid], cB1[2 * tid + 1]);
    if (tid < 8) sB2p[tid] = pack2(cB2[2 * tid], cB2[2 * tid + 1]);
    __syncthreads();

    for (int tile = blockIdx.x; tile < ntiles; tile += gridDim.x) {
        const int p = tile * 128 + tid;
        const int pc = min(p, n - 1);

        // ---- owner: encoders -> corner metadata
        {
            float gx[2], gy[2];
            float a0 = pos[2 * pc], a1 = pos[2 * pc + 1];
            float e0 = dir[2 * pc], e1 = dir[2 * pc + 1];
            encode(a0, a1, gx[0], gy[0]);
            encode(e0, e1, gx[1], gy[1]);
#pragma unroll
            for (int g = 0; g < 2; g++) {
                float x = gx[g], y = gy[g];
                int x0 = min((int)x, 255), y0 = min((int)y, 255);
                float xf = x - (float)x0, yf = y - (float)y0;
                int x1 = min(x0 + 1, 255), y1 = min(y0 + 1, 255);
                u32 otl = (u32)(y0 * 256 + x0) * 128u;
                u32 otr = (u32)(y0 * 256 + x1) * 128u;
                u32 obl = (u32)(y1 * 256 + x0) * 128u;
                u32 obr = (u32)(y1 * 256 + x1) * 128u;
                float wtl = (1.0f - xf) * (1.0f - yf);
                float wtr = xf * (1.0f - yf);
                float wbl = (1.0f - xf) * yf;
                float wbr = xf * yf;
                s_meta[warp][lane][g * 4 + 0] = (u64)otl | ((u64)__float_as_uint(wtl) << 32);
                s_meta[warp][lane][g * 4 + 1] = (u64)otr | ((u64)__float_as_uint(wtr) << 32);
                s_meta[warp][lane][g * 4 + 2] = (u64)obl | ((u64)__float_as_uint(wbl) << 32);
                s_meta[warp][lane][g * 4 + 3] = (u64)obr | ((u64)__float_as_uint(wbr) << 32);
            }
        }
        __syncwarp();

        // ---- FC1 accumulators (64 outs = 32 packed), init with bias from smem
        u64 h1[32];
#pragma unroll
        for (int q = 0; q < 32; q++) h1[q] = sB1p[q];

        // ---- per grid: warp-coop gather+blend -> stage -> FC1 partial
#pragma unroll 1
        for (int g = 0; g < 2; g++) {
            const float *gbase = (g == 0) ? pos_grid : dir_grid;
            // loader: 8 lanes per row, blend 4 corners in regs
#pragma unroll
            for (int i = 0; i < 8; i++) {
                int row = i * 4 + grp;
                const u64 *m = &s_meta[warp][row][g * 4];
                u64 acc01 = 0, acc23 = 0;
#pragma unroll
                for (int c = 0; c < 4; c++) {
                    u64 mw = m[c];
                    u32 off = (u32)mw;
                    float w = __uint_as_float((u32)(mw >> 32));
                    float4 v = __ldg((const float4 *)((const char *)gbase + off) + f);
                    u64 wv = pack2(w, w);
                    fma2(acc01, wv, pack2(v.x, v.y));
                    fma2(acc23, wv, pack2(v.z, v.w));
                }
                float2 lo = unpack2(acc01), hi = unpack2(acc23);
                s_stage[warp][row][f] = make_float4(lo.x, lo.y, hi.x, hi.y);
            }
            __syncwarp();

            // owner: FC1 partial, weights split shared(outs 0..35)/const(outs 36..63)
#pragma unroll
            for (int j = 0; j < 8; j++) {
                float4 v4 = s_stage[warp][lane][j];
                int base = g * 32 + 4 * j;
#pragma unroll
                for (int k = 0; k < 4; k++) {
                    float fv_s = (k == 0) ? v4.x : (k == 1) ? v4.y : (k == 2) ? v4.z : v4.w;
                    u64 fv = pack2(fv_s, fv_s);
                    const ulonglong2 *ws = (const ulonglong2 *)&sW1p[base + k][0];
#pragma unroll
                    for (int q = 0; q < 9; q++) {
                        ulonglong2 wq = ws[q];
                        fma2(h1[2 * q], fv, wq.x);
                        fma2(h1[2 * q + 1], fv, wq.y);
                    }
                    const ulonglong2 *wc = (const ulonglong2 *)(cW1 + (base + k) * 64 + 36);
#pragma unroll
                    for (int q = 0; q < 7; q++) {
                        ulonglong2 wq = wc[q];
                        fma2(h1[18 + 2 * q], fv, wq.x);
                        fma2(h1[19 + 2 * q], fv, wq.y);
                    }
                }
            }
            __syncwarp();
        }

        // ---- FC2: 64 -> 16, weights split shared(outs 0..11)/const(outs 12..15)
        u64 h2[8];
#pragma unroll
        for (int q = 0; q < 8; q++) h2[q] = sB2p[q];
#pragma unroll
        for (int q = 0; q < 32; q++) {
            float2 v = unpack2(h1[q]);
            float a0 = leaky(v.x), a1 = leaky(v.y);
            u64 a0v = pack2(a0, a0), a1v = pack2(a1, a1);
            const ulonglong2 *s0 = (const ulonglong2 *)&sW2p[2 * q][0];
            const ulonglong2 *s1 = (const ulonglong2 *)&sW2p[2 * q + 1][0];
#pragma unroll
            for (int r = 0; r < 3; r++) {
                ulonglong2 wa = s0[r];
                fma2(h2[2 * r], a0v, wa.x);
                fma2(h2[2 * r + 1], a0v, wa.y);
                ulonglong2 wb = s1[r];
                fma2(h2[2 * r], a1v, wb.x);
                fma2(h2[2 * r + 1], a1v, wb.y);
            }
            ulonglong2 c0 = *(const ulonglong2 *)(cW2 + (2 * q) * 16 + 12);
            ulonglong2 c1 = *(const ulonglong2 *)(cW2 + (2 * q + 1) * 16 + 12);
            fma2(h2[6], a0v, c0.x);
            fma2(h2[7], a0v, c0.y);
            fma2(h2[6], a1v, c1.x);
            fma2(h2[7], a1v, c1.y);
        }

        // ---- head
        float a2[16];
#pragma unroll
        for (int q = 0; q < 8; q++) {
            float2 v = unpack2(h2[q]);
            a2[2 * q] = leaky(v.x);
            a2[2 * q + 1] = leaky(v.y);
        }
        float3 o = head(a2);

        if (p < n) {
            out[p * 3 + 0] = o.x;
            out[p * 3 + 1] = o.y;
            out[p * 3 + 2] = o.z;
        }
    }
}

extern "C" void kernel_launch(void *const *d_in, const int *in_sizes, int n_in,
                              void *d_out, int out_size)
{
    const float *pos = (const float *)d_in[0];
    const float *dir = (const float *)d_in[1];
    const float *pos_grid = (const float *)d_in[2];
    const float *dir_grid = (const float *)d_in[3];

    cudaMemcpyToSymbolAsync(cEnc, d_in[4], 8 * sizeof(float), 0, cudaMemcpyDeviceToDevice, 0);
    cudaMemcpyToSymbolAsync(cEnc, d_in[5], 4 * sizeof(float), 8 * sizeof(float), cudaMemcpyDeviceToDevice, 0);
    cudaMemcpyToSymbolAsync(cEnc, d_in[6], 12 * sizeof(float), 12 * sizeof(float), cudaMemcpyDeviceToDevice, 0);
    cudaMemcpyToSymbolAsync(cEnc, d_in[7], 3 * sizeof(float), 24 * sizeof(float), cudaMemcpyDeviceToDevice, 0);
    cudaMemcpyToSymbolAsync(cW1, d_in[8], 64 * 64 * sizeof(float), 0, cudaMemcpyDeviceToDevice, 0);
    cudaMemcpyToSymbolAsync(cB1, d_in[9], 64 * sizeof(float), 0, cudaMemcpyDeviceToDevice, 0);
    cudaMemcpyToSymbolAsync(cW2, d_in[10], 64 * 16 * sizeof(float), 0, cudaMemcpyDeviceToDevice, 0);
    cudaMemcpyToSymbolAsync(cB2, d_in[11], 16 * sizeof(float), 0, cudaMemcpyDeviceToDevice, 0);
    cudaMemcpyToSymbolAsync(cW3, d_in[12], 16 * 8 * sizeof(float), 0, cudaMemcpyDeviceToDevice, 0);
    cudaMemcpyToSymbolAsync(cB3, d_in[13], 8 * sizeof(float), 0, cudaMemcpyDeviceToDevice, 0);
    cudaMemcpyToSymbolAsync(cW4, d_in[14], 8 * 3 * sizeof(float), 0, cudaMemcpyDeviceToDevice, 0);
    cudaMemcpyToSymbolAsync(cB4, d_in[15], 3 * sizeof(float), 0, cudaMemcpyDeviceToDevice, 0);

    float *out = (float *)d_out;
    int n = in_sizes[0] / 2;
    int ntiles = (n + 127) / 128;
    int blocks = 148 * 5;
    if (blocks > ntiles) blocks = ntiles;
    gridnet_split<<<blocks, 128>>>(pos, dir, pos_grid, dir_grid, out, n, ntiles);
}